// round 1
// baseline (speedup 1.0000x reference)
#include <cuda_runtime.h>
#include <cstdint>

// ---------------------------------------------------------------------------
// QuanvolutionSamplerHybrid — closed-form quantum filter + fused linear+logsoftmax
//
// Layout: block = 32 images (staged in smem), 14 warps; warp w handles patch
// row w (14 patches), lane = image. All lanes in a warp share the same patch
// -> weight loads are uniform-address (broadcast).
//
// Circuit closed form (verified algebraically):
//   a = [[x0,x1],[y0,y1]],  after 8x (CX; RY(p0)):
//   x0 = q*C9 + r*c0 ; x1 = q*C9 - r*c0
//   y1 = q*S9 - r*s0 ; y0 = q*S9 + r*s0
//   where q=(c1+s1)/2, r=(c1-s1)/2, (C9,S9)=cos/sin(4.5*p0),
//   (ci,si)=cos/sin(pi/2).
// ---------------------------------------------------------------------------

#define IMGS_PER_BLOCK 32
#define WARPS 14
#define THREADS (WARPS * 32)
#define IMG_STRIDE 785                 // odd -> conflict-free image-strided LDS
#define SMEM_FLOATS (IMGS_PER_BLOCK * IMG_STRIDE)
#define SMEM_BYTES (SMEM_FLOATS * 4)   // 100,480 B -> 2 blocks / SM

// Repacked weights: [patch j][class c][feat k], k=0..15 filter, 16..19 sampler
__device__ __align__(16) float g_wpack[196 * 200];

__global__ void prep_kernel(const float* __restrict__ fc_w) {
    int idx = blockIdx.x * 256 + threadIdx.x;
    if (idx >= 196 * 200) return;
    int j = idx / 200;
    int r = idx - j * 200;
    int c = r / 20;
    int k = r - c * 20;
    float v;
    if (k < 16) v = fc_w[c * 3920 + j * 16 + k];
    else        v = fc_w[c * 3920 + 3136 + j * 4 + (k - 16)];
    g_wpack[idx] = v;
}

// cos(p/2), sin(p/2) for p in [0,1): degree-7/6 Taylor, < 2e-6 abs error
__device__ __forceinline__ void cs_half(float p, float& c, float& s) {
    float t = p * p;
    s = p * fmaf(t, fmaf(t, fmaf(t, -1.5500992e-6f, 2.6041668e-4f),
                         -2.0833334e-2f), 0.5f);
    c = fmaf(t, fmaf(t, fmaf(t, -2.1701389e-5f, 2.6041667e-3f),
                     -0.125f), 1.0f);
}

__global__ __launch_bounds__(THREADS, 2)
void quanv_kernel(const float* __restrict__ x,
                  const float* __restrict__ fc_b,
                  float* __restrict__ out) {
    extern __shared__ float sm[];
    const int tid = threadIdx.x;

    // ---- Stage 32 images (25088 floats) coalesced into padded smem ----
    const float4* xb =
        reinterpret_cast<const float4*>(x + (size_t)blockIdx.x * (IMGS_PER_BLOCK * 784));
    #pragma unroll
    for (int i = tid; i < IMGS_PER_BLOCK * 784 / 4; i += THREADS) {
        float4 v = xb[i];
        int g = i * 4;
        int img = g / 784;
        int q = g - img * 784;
        float* d = sm + img * IMG_STRIDE + q;
        d[0] = v.x; d[1] = v.y; d[2] = v.z; d[3] = v.w;
    }
    __syncthreads();

    const int w = tid >> 5;
    const int lane = tid & 31;

    float acc[10];
    #pragma unroll
    for (int c = 0; c < 10; c++) acc[c] = 0.0f;

    // warp w owns patch row w: image rows 2w and 2w+1
    const float* sp = sm + lane * IMG_STRIDE + w * 56;
    const float* wp0 = g_wpack + w * 14 * 200;

    #pragma unroll 1
    for (int pj = 0; pj < 14; pj++) {
        float p0 = sp[2 * pj];
        float p1 = sp[2 * pj + 1];
        float p2 = sp[2 * pj + 28];
        float p3 = sp[2 * pj + 29];

        float c0, s0, c1, s1, c2d, s2d, c3d, s3d;
        cs_half(p0, c0, s0);
        cs_half(p1, c1, s1);
        cs_half(p2, c2d, s2d);
        cs_half(p3, c3d, s3d);

        float S9, C9;
        __sincosf(4.5f * p0, &S9, &C9);

        float qh = 0.5f * (c1 + s1);
        float rh = 0.5f * (c1 - s1);
        float tC = qh * C9, tS = qh * S9;
        float rc = rh * c0, rs = rh * s0;
        float x0 = tC + rc, x1 = tC - rc;
        float y1 = tS - rs, y0 = tS + rs;

        float q00 = x0 * x0, q01 = x1 * x1, q10 = y0 * y0, q11 = y1 * y1;
        float p2q = s2d * s2d, p3q = s3d * s3d;
        float om2 = 1.0f - p2q, om3 = 1.0f - p3q;
        float m0 = om2 * om3, m1 = om2 * p3q, m2 = p2q * om3, m3 = p2q * p3q;
        float s0q = s0 * s0, om0 = 1.0f - s0q;

        float f[20];
        f[0]  = q00 * m0; f[1]  = q00 * m1; f[2]  = q00 * m2; f[3]  = q00 * m3;
        f[4]  = q01 * m0; f[5]  = q01 * m1; f[6]  = q01 * m2; f[7]  = q01 * m3;
        f[8]  = q10 * m0; f[9]  = q10 * m1; f[10] = q10 * m2; f[11] = q10 * m3;
        f[12] = q11 * m0; f[13] = q11 * m1; f[14] = q11 * m2; f[15] = q11 * m3;
        f[16] = om0 * om3; f[17] = om0 * p3q; f[18] = s0q * om3; f[19] = s0q * p3q;

        const float* wp = wp0 + pj * 200;
        #pragma unroll
        for (int c = 0; c < 10; c++) {
            const float4* w4 = reinterpret_cast<const float4*>(wp + c * 20);
            float4 wa = w4[0], wb = w4[1], wc = w4[2], wd = w4[3], we = w4[4];
            float wk[20] = {wa.x, wa.y, wa.z, wa.w,
                            wb.x, wb.y, wb.z, wb.w,
                            wc.x, wc.y, wc.z, wc.w,
                            wd.x, wd.y, wd.z, wd.w,
                            we.x, we.y, we.z, we.w};
            float a = acc[c];
            #pragma unroll
            for (int k = 0; k < 20; k++) a = fmaf(f[k], wk[k], a);
            acc[c] = a;
        }
    }

    // ---- Cross-warp reduction (reuse pixel smem) ----
    __syncthreads();
    float* part = sm;                       // [WARPS][32][10]
    #pragma unroll
    for (int c = 0; c < 10; c++)
        part[w * 320 + lane * 10 + c] = acc[c];
    __syncthreads();

    float* L = sm + WARPS * 320;            // [320] logits
    if (tid < 320) {
        float s = 0.0f;
        #pragma unroll
        for (int ww = 0; ww < WARPS; ww++) s += part[ww * 320 + tid];
        s += fc_b[tid % 10];
        L[tid] = s;
    }
    __syncthreads();

    float* lse = L + 320;                   // [32]
    if (tid < 32) {
        const float* Lr = L + tid * 10;
        float mx = Lr[0];
        #pragma unroll
        for (int c = 1; c < 10; c++) mx = fmaxf(mx, Lr[c]);
        float se = 0.0f;
        #pragma unroll
        for (int c = 0; c < 10; c++) se += __expf(Lr[c] - mx);
        lse[tid] = mx + __logf(se);
    }
    __syncthreads();

    if (tid < 320)
        out[blockIdx.x * 320 + tid] = L[tid] - lse[tid / 10];
}

extern "C" void kernel_launch(void* const* d_in, const int* in_sizes, int n_in,
                              void* d_out, int out_size) {
    const float* x    = (const float*)d_in[0];   // (8192,1,28,28)
    const float* fc_w = (const float*)d_in[1];   // (10,3920)
    const float* fc_b = (const float*)d_in[2];   // (10,)
    float* out = (float*)d_out;                  // (8192,10)
    (void)in_sizes; (void)n_in; (void)out_size;

    cudaFuncSetAttribute(quanv_kernel,
                         cudaFuncAttributeMaxDynamicSharedMemorySize, SMEM_BYTES);

    prep_kernel<<<(196 * 200 + 255) / 256, 256>>>(fc_w);
    quanv_kernel<<<8192 / IMGS_PER_BLOCK, THREADS, SMEM_BYTES>>>(x, fc_b, out);
}

// round 3
// speedup vs baseline: 1.0439x; 1.0439x over previous
#include <cuda_runtime.h>
#include <cstdint>

// ---------------------------------------------------------------------------
// QuanvolutionSamplerHybrid — closed-form circuit, f32x2 patch-pair matvec.
//
// Warp w handles patch rows 2w,2w+1; lane = image. Each loop iteration
// processes TWO adjacent patches packed into f32x2 lanes (both contribute to
// the same image logits, so packed accumulators just get .lo+.hi at the end).
// ---------------------------------------------------------------------------

#define IMGS_PER_BLOCK 32
#define WARPS 7
#define THREADS (WARPS * 32)
#define IMG_STRIDE 788                 // mult of 4 (float4 aligned); conflict-free
#define SMEM_FLOATS (IMGS_PER_BLOCK * IMG_STRIDE)
#define SMEM_BYTES (SMEM_FLOATS * 4)   // 100,864 B -> 2 blocks / SM

typedef unsigned long long ull;

// weights packed [row(14)][pair(7)][class(10)][k(20)][2: patchA/patchB]
__device__ __align__(16) float g_wpack2[14 * 7 * 10 * 20 * 2];

__global__ void prep_kernel(const float* __restrict__ fc_w) {
    int idx = blockIdx.x * 256 + threadIdx.x;
    if (idx >= 39200) return;
    int pairIdx = idx / 400;           // row*7 + t
    int rem = idx - pairIdx * 400;
    int c = rem / 40;
    int kh = rem - c * 40;             // FIXED: was (rem & 39), wrong for rem>=40
    int k = kh >> 1;
    int h = kh & 1;
    int row = pairIdx / 7;
    int t = pairIdx - row * 7;
    int j = row * 14 + 2 * t + h;      // patch index 0..195
    float v;
    if (k < 16) v = fc_w[c * 3920 + j * 16 + k];
    else        v = fc_w[c * 3920 + 3136 + j * 4 + (k - 16)];
    g_wpack2[idx] = v;
}

// ---- f32x2 helpers ----
__device__ __forceinline__ ull pk2(float lo, float hi) {
    ull r; asm("mov.b64 %0,{%1,%2};" : "=l"(r) : "f"(lo), "f"(hi)); return r;
}
__device__ __forceinline__ void upk2(ull v, float& lo, float& hi) {
    asm("mov.b64 {%0,%1},%2;" : "=f"(lo), "=f"(hi) : "l"(v));
}
__device__ __forceinline__ ull add2(ull a, ull b) {
    ull d; asm("add.rn.f32x2 %0,%1,%2;" : "=l"(d) : "l"(a), "l"(b)); return d;
}
__device__ __forceinline__ ull mul2(ull a, ull b) {
    ull d; asm("mul.rn.f32x2 %0,%1,%2;" : "=l"(d) : "l"(a), "l"(b)); return d;
}
__device__ __forceinline__ ull fma2(ull a, ull b, ull c) {
    ull d; asm("fma.rn.f32x2 %0,%1,%2,%3;" : "=l"(d) : "l"(a), "l"(b), "l"(c)); return d;
}

// cos(p/2), sin(p/2) packed, p in [0,1): Taylor, < 2e-6 abs error
__device__ __forceinline__ void cs_half2(ull p, ull& c, ull& s,
                                         ull K_S3, ull K_S2, ull K_S1, ull K_S0,
                                         ull K_C3, ull K_C2, ull K_C1, ull ONE) {
    ull t = mul2(p, p);
    s = mul2(p, fma2(t, fma2(t, fma2(t, K_S3, K_S2), K_S1), K_S0));
    c = fma2(t, fma2(t, fma2(t, K_C3, K_C2), K_C1), ONE);
}

__global__ __launch_bounds__(THREADS, 2)
void quanv_kernel(const float* __restrict__ x,
                  const float* __restrict__ fc_b,
                  float* __restrict__ out) {
    extern __shared__ float sm[];
    const int tid = threadIdx.x;

    // ---- Stage 32 images coalesced into padded smem (float4 aligned) ----
    const float4* xb =
        reinterpret_cast<const float4*>(x + (size_t)blockIdx.x * (IMGS_PER_BLOCK * 784));
    #pragma unroll
    for (int i = tid; i < IMGS_PER_BLOCK * 784 / 4; i += THREADS) {
        float4 v = xb[i];
        int g = i * 4;
        int img = g / 784;
        int q = g - img * 784;
        *reinterpret_cast<float4*>(sm + img * IMG_STRIDE + q) = v;
    }
    __syncthreads();

    const int w = tid >> 5;
    const int lane = tid & 31;

    const ull ONE  = pk2(1.0f, 1.0f);
    const ull N1   = pk2(-1.0f, -1.0f);
    const ull H2   = pk2(0.5f, 0.5f);
    const ull NH2  = pk2(-0.5f, -0.5f);
    const ull K_S3 = pk2(-1.5500992e-6f, -1.5500992e-6f);
    const ull K_S2 = pk2(2.6041668e-4f, 2.6041668e-4f);
    const ull K_S1 = pk2(-2.0833334e-2f, -2.0833334e-2f);
    const ull K_S0 = pk2(0.5f, 0.5f);
    const ull K_C3 = pk2(-2.1701389e-5f, -2.1701389e-5f);
    const ull K_C2 = pk2(2.6041667e-3f, 2.6041667e-3f);
    const ull K_C1 = pk2(-0.125f, -0.125f);

    ull acc2[10];
    #pragma unroll
    for (int c = 0; c < 10; c++) acc2[c] = 0ULL;

    #pragma unroll 1
    for (int rr = 0; rr < 2; rr++) {
        const int row = 2 * w + rr;                       // patch row 0..13
        const float* sp = sm + lane * IMG_STRIDE + row * 56;
        const ulonglong2* wrow =
            reinterpret_cast<const ulonglong2*>(g_wpack2 + row * 7 * 400);

        #pragma unroll 1
        for (int t = 0; t < 7; t++) {
            // row-A pixels: (p0A, p1A, p0B, p1B); row-B: (p2A, p3A, p2B, p3B)
            float4 A = *reinterpret_cast<const float4*>(sp + 4 * t);
            float4 Bv = *reinterpret_cast<const float4*>(sp + 28 + 4 * t);

            ull P0 = pk2(A.x, A.z);
            ull P1 = pk2(A.y, A.w);
            ull P2 = pk2(Bv.x, Bv.z);
            ull P3 = pk2(Bv.y, Bv.w);

            ull C0, S0, C1, S1, C2, S2, C3, S3;
            cs_half2(P0, C0, S0, K_S3, K_S2, K_S1, K_S0, K_C3, K_C2, K_C1, ONE);
            cs_half2(P1, C1, S1, K_S3, K_S2, K_S1, K_S0, K_C3, K_C2, K_C1, ONE);
            cs_half2(P2, C2, S2, K_S3, K_S2, K_S1, K_S0, K_C3, K_C2, K_C1, ONE);
            cs_half2(P3, C3, S3, K_S3, K_S2, K_S1, K_S0, K_C3, K_C2, K_C1, ONE);

            float s9a, c9a, s9b, c9b;
            __sincosf(4.5f * A.x, &s9a, &c9a);
            __sincosf(4.5f * A.z, &s9b, &c9b);
            ull C9 = pk2(c9a, c9b);
            ull S9 = pk2(s9a, s9b);

            ull CH = mul2(C1, H2);
            ull qh = fma2(S1, H2, CH);
            ull rh = fma2(S1, NH2, CH);
            ull tC = mul2(qh, C9), tS = mul2(qh, S9);
            ull rc = mul2(rh, C0), rs = mul2(rh, S0);
            ull x0 = add2(tC, rc), x1 = fma2(rc, N1, tC);
            ull y0 = add2(tS, rs), y1 = fma2(rs, N1, tS);

            ull Q0 = mul2(x0, x0), Q1 = mul2(x1, x1);
            ull Q2 = mul2(y0, y0), Q3 = mul2(y1, y1);
            ull p2q = mul2(S2, S2), p3q = mul2(S3, S3);
            ull o2 = fma2(p2q, N1, ONE), o3 = fma2(p3q, N1, ONE);
            ull M0 = mul2(o2, o3), M1 = mul2(o2, p3q);
            ull M2 = mul2(p2q, o3), M3 = mul2(p2q, p3q);
            ull s0q = mul2(S0, S0), o0 = fma2(s0q, N1, ONE);

            ull F[20];
            F[0]  = mul2(Q0, M0); F[1]  = mul2(Q0, M1); F[2]  = mul2(Q0, M2); F[3]  = mul2(Q0, M3);
            F[4]  = mul2(Q1, M0); F[5]  = mul2(Q1, M1); F[6]  = mul2(Q1, M2); F[7]  = mul2(Q1, M3);
            F[8]  = mul2(Q2, M0); F[9]  = mul2(Q2, M1); F[10] = mul2(Q2, M2); F[11] = mul2(Q2, M3);
            F[12] = mul2(Q3, M0); F[13] = mul2(Q3, M1); F[14] = mul2(Q3, M2); F[15] = mul2(Q3, M3);
            F[16] = mul2(o0, o3); F[17] = mul2(o0, p3q);
            F[18] = mul2(s0q, o3); F[19] = mul2(s0q, p3q);

            const ulonglong2* wp = wrow + t * 100;   // 10 classes * 10 ull2
            #pragma unroll
            for (int c = 0; c < 10; c++) {
                ull a = acc2[c];
                #pragma unroll
                for (int q = 0; q < 10; q++) {
                    ulonglong2 wv = wp[c * 10 + q];
                    a = fma2(F[2 * q], wv.x, a);
                    a = fma2(F[2 * q + 1], wv.y, a);
                }
                acc2[c] = a;
            }
        }
    }

    // collapse packed halves: both patches feed the same image logit
    float acc[10];
    #pragma unroll
    for (int c = 0; c < 10; c++) {
        float lo, hi;
        upk2(acc2[c], lo, hi);
        acc[c] = lo + hi;
    }

    // ---- Cross-warp reduction (reuse pixel smem) ----
    __syncthreads();
    float* part = sm;                       // [WARPS][32][10]
    #pragma unroll
    for (int c = 0; c < 10; c++)
        part[w * 320 + lane * 10 + c] = acc[c];
    __syncthreads();

    float* L = sm + WARPS * 320;            // [320] logits
    for (int idx = tid; idx < 320; idx += THREADS) {
        float s = 0.0f;
        #pragma unroll
        for (int ww = 0; ww < WARPS; ww++) s += part[ww * 320 + idx];
        s += fc_b[idx % 10];
        L[idx] = s;
    }
    __syncthreads();

    float* lse = L + 320;                   // [32]
    if (tid < 32) {
        const float* Lr = L + tid * 10;
        float mx = Lr[0];
        #pragma unroll
        for (int c = 1; c < 10; c++) mx = fmaxf(mx, Lr[c]);
        float se = 0.0f;
        #pragma unroll
        for (int c = 0; c < 10; c++) se += __expf(Lr[c] - mx);
        lse[tid] = mx + __logf(se);
    }
    __syncthreads();

    for (int idx = tid; idx < 320; idx += THREADS)
        out[blockIdx.x * 320 + idx] = L[idx] - lse[idx / 10];
}

extern "C" void kernel_launch(void* const* d_in, const int* in_sizes, int n_in,
                              void* d_out, int out_size) {
    const float* x    = (const float*)d_in[0];   // (8192,1,28,28)
    const float* fc_w = (const float*)d_in[1];   // (10,3920)
    const float* fc_b = (const float*)d_in[2];   // (10,)
    float* out = (float*)d_out;                  // (8192,10)
    (void)in_sizes; (void)n_in; (void)out_size;

    cudaFuncSetAttribute(quanv_kernel,
                         cudaFuncAttributeMaxDynamicSharedMemorySize, SMEM_BYTES);

    prep_kernel<<<(39200 + 255) / 256, 256>>>(fc_w);
    quanv_kernel<<<8192 / IMGS_PER_BLOCK, THREADS, SMEM_BYTES>>>(x, fc_b, out);
}